// round 5
// baseline (speedup 1.0000x reference)
#include <cuda_runtime.h>

// ---------------------------------------------------------------------------
// EMAVectorQuantizer: fused fp32 GEMM+argmin (f32x2 packed FMA), then EMA update.
// Argmin emulates the reference's fp32 rounding exactly:
//   d2 = fl( fl( xs - fl(2*dot) ) + en ), ties -> lowest index,
// with dot accumulated sequential-k single-accumulator fma (Eigen NEON order)
// and xs accumulated in XLA:CPU vectorized-reduce order (8 stride-8 chains,
// lanewise pair-add, then ((l0+l2)+(l1+l3)) horizontal).
// ---------------------------------------------------------------------------

#define N_ROWS 16384
#define DDIM   512
#define KCODES 8192

#define OFF_Q  ((size_t)0)
#define OFF_T  ((size_t)8388608)
#define OFF_L  ((size_t)8404992)
#define OFF_E  ((size_t)8404993)
#define OFF_CS ((size_t)12599297)
#define OFF_W  ((size_t)12607489)

__device__ float g_enorm[KCODES];
__device__ float g_xs[N_ROWS];
__device__ int   g_idx[N_ROWS];
__device__ float g_sumsq;
__device__ float g_S;

// ---- packed f32x2 helpers (Blackwell FFMA2: 2 FMA per issue slot) ----------
__device__ __forceinline__ void ffma2(unsigned long long& d,
                                      unsigned long long a,
                                      unsigned long long b) {
    asm("fma.rn.f32x2 %0, %1, %2, %0;" : "+l"(d) : "l"(a), "l"(b));
}
__device__ __forceinline__ unsigned long long dup2(float x) {
    unsigned long long r;
    unsigned u = __float_as_uint(x);
    asm("mov.b64 %0, {%1, %1};" : "=l"(r) : "r"(u));
    return r;
}
__device__ __forceinline__ float2 u2f2(unsigned long long v) {
    unsigned lo, hi;
    asm("mov.b64 {%0, %1}, %2;" : "=r"(lo), "=r"(hi) : "l"(v));
    float2 r;
    r.x = __uint_as_float(lo);
    r.y = __uint_as_float(hi);
    return r;
}

// ---- kernel 0: xs[n] = sum(x_n^2) in XLA:CPU vectorized-reduce order -------
// 8 stride-8 scalar chains (acc += fl(x*x), no fma), then
// lane_l = fl(A_l + A_{l+4}); xs = fl( fl(l0+l2) + fl(l1+l3) ).
__global__ void k_xnorm(const float* __restrict__ X) {
    int gid = blockIdx.x * blockDim.x + threadIdx.x;  // 8 threads per row
    int n = gid >> 3;
    int l = gid & 7;
    if (n >= N_ROWS) return;
    const float* xr = X + (size_t)n * DDIM;
    float a = 0.0f;
#pragma unroll 8
    for (int t = 0; t < DDIM / 8; ++t) {
        float v = xr[t * 8 + l];
        a = __fadd_rn(a, __fmul_rn(v, v));
    }
    const unsigned m = 0xffffffffu;
    float b   = __shfl_down_sync(m, a, 4);
    float tot = __fadd_rn(a, b);              // valid for l < 4
    float c   = __shfl_down_sync(m, tot, 2);
    float u   = __fadd_rn(tot, c);            // valid for l < 2
    float d   = __shfl_down_sync(m, u, 1);
    float xs  = __fadd_rn(u, d);              // valid for l == 0
    if (l == 0) g_xs[n] = xs;
}

// ---- kernel 1: ||e_k||^2 per code row, + zero the loss accumulator ---------
__global__ void k_enorm(const float* __restrict__ E) {
    if (blockIdx.x == 0 && threadIdx.x == 0) g_sumsq = 0.0f;
    int warp = (blockIdx.x * blockDim.x + threadIdx.x) >> 5;
    int lane = threadIdx.x & 31;
    if (warp >= KCODES) return;
    const float4* p = reinterpret_cast<const float4*>(E + (size_t)warp * DDIM);
    float s = 0.0f;
#pragma unroll
    for (int i = 0; i < 4; ++i) {
        float4 v = p[lane + 32 * i];
        s += v.x * v.x + v.y * v.y + v.z * v.z + v.w * v.w;
    }
#pragma unroll
    for (int o = 16; o > 0; o >>= 1) s += __shfl_xor_sync(0xffffffffu, s, o);
    if (lane == 0) g_enorm[warp] = s;
}

// ---- kernel 2: fused fp32 GEMM (X @ E^T) + per-row argmin ------------------
// BM=BN=128, BK=16, 256 threads, 8x8 microtile, rows packed pairwise (f32x2).
// Dot accumulation: single accumulator, k strictly ascending, fma per step
// (bit-matches Eigen NEON gebp). Score: fl(fl(xs - 2*dot) + en), ties->lowest.
__global__ void __launch_bounds__(256, 1)
k_argmin(const float* __restrict__ X, const float* __restrict__ E) {
    __shared__ __align__(16) float sm[4096];  // As[16][128] | Bs[16][128] = 16KB

    const int tid  = threadIdx.x;
    const int m0   = blockIdx.x * 128;
    const int row0 = (tid & 15) * 8;
    const int col0 = (tid >> 4) * 8;

    float xsr[8];
#pragma unroll
    for (int i = 0; i < 8; ++i) xsr[i] = g_xs[m0 + row0 + i];

    float bestv[8];
    int   besti[8];
#pragma unroll
    for (int i = 0; i < 8; ++i) {
        bestv[i] = __int_as_float(0x7f800000);
        besti[i] = 0;
    }

    float4 pa[2], pb[2];
    auto LD = [&](int nt, int kc) {
#pragma unroll
        for (int rep = 0; rep < 2; ++rep) {
            int s   = tid + rep * 256;
            int row = s >> 2;
            int c4  = (s & 3) << 2;
            pa[rep] = *reinterpret_cast<const float4*>(
                X + (size_t)(m0 + row) * DDIM + kc * 16 + c4);
            pb[rep] = *reinterpret_cast<const float4*>(
                E + (size_t)(nt * 128 + row) * DDIM + kc * 16 + c4);
        }
    };
    LD(0, 0);

    for (int nt = 0; nt < KCODES / 128; ++nt) {
        unsigned long long acc[4][8];
#pragma unroll
        for (int p = 0; p < 4; ++p)
#pragma unroll
            for (int j = 0; j < 8; ++j) acc[p][j] = 0ULL;

        for (int kc = 0; kc < DDIM / 16; ++kc) {
            __syncthreads();
#pragma unroll
            for (int rep = 0; rep < 2; ++rep) {
                int s   = tid + rep * 256;
                int row = s >> 2;
                int c4  = (s & 3) << 2;
                sm[(c4 + 0) * 128 + row] = pa[rep].x;
                sm[(c4 + 1) * 128 + row] = pa[rep].y;
                sm[(c4 + 2) * 128 + row] = pa[rep].z;
                sm[(c4 + 3) * 128 + row] = pa[rep].w;
                sm[2048 + (c4 + 0) * 128 + row] = pb[rep].x;
                sm[2048 + (c4 + 1) * 128 + row] = pb[rep].y;
                sm[2048 + (c4 + 2) * 128 + row] = pb[rep].z;
                sm[2048 + (c4 + 3) * 128 + row] = pb[rep].w;
            }
            __syncthreads();
            {   // prefetch next tile's gmem loads; latency hidden by compute
                int nn = nt, nk = kc + 1;
                if (nk == DDIM / 16) { nk = 0; ++nn; }
                if (nn < KCODES / 128) LD(nn, nk);
            }
#pragma unroll
            for (int kk = 0; kk < 16; ++kk) {
                const ulonglong2* ap =
                    reinterpret_cast<const ulonglong2*>(&sm[kk * 128 + row0]);
                ulonglong2 A01 = ap[0];
                ulonglong2 A23 = ap[1];
                const float4* bp =
                    reinterpret_cast<const float4*>(&sm[2048 + kk * 128 + col0]);
                float4 b03 = bp[0], b47 = bp[1];
                float bs[8] = {b03.x, b03.y, b03.z, b03.w,
                               b47.x, b47.y, b47.z, b47.w};
#pragma unroll
                for (int j = 0; j < 8; ++j) {
                    unsigned long long bb = dup2(bs[j]);
                    ffma2(acc[0][j], A01.x, bb);
                    ffma2(acc[1][j], A01.y, bb);
                    ffma2(acc[2][j], A23.x, bb);
                    ffma2(acc[3][j], A23.y, bb);
                }
            }
        }
        // epilogue: emulate reference rounding:
        //   s = fl( fl(xs - 2*dot) + en )   (2*dot exact; en provably no-op)
        // strict < with ascending cols => lowest index on ties.
#pragma unroll
        for (int j = 0; j < 8; ++j) {
            int col  = nt * 128 + col0 + j;
            float en = g_enorm[col];
#pragma unroll
            for (int p = 0; p < 4; ++p) {
                float2 v = u2f2(acc[p][j]);
                float s0 = __fadd_rn(__fadd_rn(xsr[2 * p + 0], -2.0f * v.x), en);
                float s1 = __fadd_rn(__fadd_rn(xsr[2 * p + 1], -2.0f * v.y), en);
                if (s0 < bestv[2 * p + 0]) { bestv[2 * p + 0] = s0; besti[2 * p + 0] = col; }
                if (s1 < bestv[2 * p + 1]) { bestv[2 * p + 1] = s1; besti[2 * p + 1] = col; }
            }
        }
    }

    // cross-thread reduction: 16 column-groups per row, tie-break lowest index
    __syncthreads();
    {
        float* sv = sm;
        int*   si = reinterpret_cast<int*>(sm + 2048);
        const int colg = tid >> 4;
#pragma unroll
        for (int i = 0; i < 8; ++i) {
            sv[(row0 + i) * 16 + colg] = bestv[i];
            si[(row0 + i) * 16 + colg] = besti[i];
        }
        __syncthreads();
        if (tid < 128) {
            float bv = __int_as_float(0x7f800000);
            int   bi = 0x7fffffff;
#pragma unroll
            for (int g = 0; g < 16; ++g) {
                float v  = sv[tid * 16 + g];
                int   ii = si[tid * 16 + g];
                if (v < bv || (v == bv && ii < bi)) { bv = v; bi = ii; }
            }
            g_idx[m0 + tid] = bi;
        }
    }
}

// ---- kernel 3: init new_w = decay*ema_w, new_cs = decay*ema_cs -------------
__global__ void k_init(const float* __restrict__ ew,
                       const float* __restrict__ ecs,
                       float* __restrict__ out) {
    size_t i = (size_t)blockIdx.x * blockDim.x + threadIdx.x;
    if (i < (size_t)KCODES * DDIM) out[OFF_W + i] = 0.99f * ew[i];
    if (i < (size_t)KCODES)        out[OFF_CS + i] = 0.99f * ecs[i];
}

// ---- kernel 4: gather quantized (STE), commitment, scatter EMA sums --------
__global__ void __launch_bounds__(128)
k_gather(const float* __restrict__ X, const float* __restrict__ E,
         float* __restrict__ out) {
    const int n   = blockIdx.x;
    const int t   = threadIdx.x;
    const int idx = g_idx[n];
    const float4 f = reinterpret_cast<const float4*>(X + (size_t)n * DDIM)[t];
    const float4 e = reinterpret_cast<const float4*>(E + (size_t)idx * DDIM)[t];
    float4 q;  // replicate reference STE arithmetic exactly: f + (e - f)
    q.x = f.x + (e.x - f.x);
    q.y = f.y + (e.y - f.y);
    q.z = f.z + (e.z - f.z);
    q.w = f.w + (e.w - f.w);
    reinterpret_cast<float4*>(out + OFF_Q + (size_t)n * DDIM)[t] = q;
    float dx = f.x - q.x, dy = f.y - q.y, dz = f.z - q.z, dw = f.w - q.w;
    float local = dx * dx + dy * dy + dz * dz + dw * dw;

    const float om = (float)(1.0 - 0.99);   // matches f32(1-0.99) in reference
    float* w = out + OFF_W + (size_t)idx * DDIM + (size_t)t * 4;
    atomicAdd(w + 0, om * f.x);
    atomicAdd(w + 1, om * f.y);
    atomicAdd(w + 2, om * f.z);
    atomicAdd(w + 3, om * f.w);

    __shared__ float red[128];
    red[t] = local;
    __syncthreads();
#pragma unroll
    for (int o = 64; o > 0; o >>= 1) {
        if (t < o) red[t] += red[t + o];
        __syncthreads();
    }
    if (t == 0) {
        atomicAdd(&g_sumsq, red[0]);
        out[OFF_T + n] = (float)idx;
        atomicAdd(out + OFF_CS + idx, om);
    }
}

// ---- kernel 5: S = sum(new_cs) ----------------------------------------------
__global__ void k_sumcs(const float* __restrict__ cs) {
    __shared__ float red[256];
    float s = 0.0f;
    for (int i = threadIdx.x; i < KCODES; i += 256) s += cs[i];
    red[threadIdx.x] = s;
    __syncthreads();
#pragma unroll
    for (int o = 128; o > 0; o >>= 1) {
        if (threadIdx.x < o) red[threadIdx.x] += red[threadIdx.x + o];
        __syncthreads();
    }
    if (threadIdx.x == 0) g_S = red[0];
}

// ---- kernel 6: new_embeddings = new_w / cs_norm ; write loss ----------------
__global__ void k_final(float* __restrict__ out) {
    size_t i = (size_t)blockIdx.x * blockDim.x + threadIdx.x;
    if (i == 0) out[OFF_L] = 0.25f * (g_sumsq / 8388608.0f);
    if (i >= (size_t)KCODES * DDIM) return;
    size_t k = i >> 9;  // D = 512
    float csn = (out[OFF_CS + k] + 1e-5f) / (g_S + (float)(8192 * 1e-5));
    out[OFF_E + i] = out[OFF_W + i] / csn;
}

// ---------------------------------------------------------------------------
extern "C" void kernel_launch(void* const* d_in, const int* in_sizes, int n_in,
                              void* d_out, int out_size) {
    const float* X   = (const float*)d_in[0];
    const float* E   = (const float*)d_in[1];
    const float* ecs = (const float*)d_in[2];
    const float* ew  = (const float*)d_in[3];
    float* out = (float*)d_out;

    k_xnorm <<<N_ROWS * 8 / 256, 256>>>(X);
    k_enorm <<<KCODES / 8, 256>>>(E);
    k_argmin<<<N_ROWS / 128, 256>>>(X, E);
    k_init  <<<(KCODES * DDIM + 255) / 256, 256>>>(ew, ecs, out);
    k_gather<<<N_ROWS, 128>>>(X, E, out);
    k_sumcs <<<1, 256>>>(out + OFF_CS);
    k_final <<<(KCODES * DDIM + 255) / 256, 256>>>(out);
}

// round 7
// speedup vs baseline: 3.1909x; 3.1909x over previous
#include <cuda_runtime.h>
#include <cuda_bf16.h>
#include <cstdint>

// ---------------------------------------------------------------------------
// EMAVectorQuantizer on GB300 (sm_103 via compute_103 PTX -> no tcgen05):
// bf16 mma.sync (HMMA) approximate GEMM + candidate capture, exact fp32
// rescoring of near-min candidates (reference-bit chain), then EMA update.
// ---------------------------------------------------------------------------

#define N_ROWS 16384
#define DDIM   512
#define KCODES 8192

#define OFF_Q  ((size_t)0)
#define OFF_T  ((size_t)8388608)
#define OFF_L  ((size_t)8404992)
#define OFF_E  ((size_t)8404993)
#define OFF_CS ((size_t)12599297)
#define OFF_W  ((size_t)12607489)

#define MARGIN 5e-4f
#define CBUF   6

__device__ __nv_bfloat16 g_ehi[(size_t)KCODES * DDIM];
__device__ float g_enorm[KCODES];
__device__ float g_xs[N_ROWS];
__device__ int   g_idx[N_ROWS];
__device__ int   g_cand[(size_t)N_ROWS * 32];
__device__ int   g_cnt[N_ROWS];
__device__ float g_sumsq;
__device__ float g_S;

// ---------------------------------------------------------------------------
__device__ __forceinline__ uint32_t packbf2(float lo, float hi) {
    __nv_bfloat162 h = __float22bfloat162_rn(make_float2(lo, hi));
    return *reinterpret_cast<uint32_t*>(&h);
}

__device__ __forceinline__ void mma16816(float& c0, float& c1, float& c2, float& c3,
                                         uint32_t a0, uint32_t a1, uint32_t a2,
                                         uint32_t a3, uint32_t b0, uint32_t b1) {
    asm volatile(
        "mma.sync.aligned.m16n8k16.row.col.f32.bf16.bf16.f32 "
        "{%0,%1,%2,%3}, {%4,%5,%6,%7}, {%8,%9}, {%0,%1,%2,%3};"
        : "+f"(c0), "+f"(c1), "+f"(c2), "+f"(c3)
        : "r"(a0), "r"(a1), "r"(a2), "r"(a3), "r"(b0), "r"(b1));
}

// ---------------------------------------------------------------------------
// kernel: E -> bf16 (hi only) + zero candidate counters
// ---------------------------------------------------------------------------
__global__ void k_splitE(const float* __restrict__ E) {
    size_t i = (size_t)blockIdx.x * blockDim.x + threadIdx.x;
    if (i < (size_t)KCODES * DDIM) g_ehi[i] = __float2bfloat16(E[i]);
    if (i < (size_t)N_ROWS) g_cnt[i] = 0;
}

// ---------------------------------------------------------------------------
// kernel: xs in XLA:CPU vectorized-reduce order (validated bit-exact in R5)
// ---------------------------------------------------------------------------
__global__ void k_xnorm(const float* __restrict__ X) {
    int gid = blockIdx.x * blockDim.x + threadIdx.x;
    int n = gid >> 3;
    int l = gid & 7;
    if (n >= N_ROWS) return;
    const float* xr = X + (size_t)n * DDIM;
    float a = 0.0f;
#pragma unroll 8
    for (int t = 0; t < DDIM / 8; ++t) {
        float v = xr[t * 8 + l];
        a = __fadd_rn(a, __fmul_rn(v, v));
    }
    const unsigned m = 0xffffffffu;
    float b   = __shfl_down_sync(m, a, 4);
    float tot = __fadd_rn(a, b);
    float c   = __shfl_down_sync(m, tot, 2);
    float u   = __fadd_rn(tot, c);
    float d   = __shfl_down_sync(m, u, 1);
    float xs  = __fadd_rn(u, d);
    if (l == 0) g_xs[n] = xs;
}

// ---------------------------------------------------------------------------
// kernel: ||e||^2 (validated) + zero loss accumulator
// ---------------------------------------------------------------------------
__global__ void k_enorm(const float* __restrict__ E) {
    if (blockIdx.x == 0 && threadIdx.x == 0) g_sumsq = 0.0f;
    int warp = (blockIdx.x * blockDim.x + threadIdx.x) >> 5;
    int lane = threadIdx.x & 31;
    if (warp >= KCODES) return;
    const float4* p = reinterpret_cast<const float4*>(E + (size_t)warp * DDIM);
    float s = 0.0f;
#pragma unroll
    for (int i = 0; i < 4; ++i) {
        float4 v = p[lane + 32 * i];
        s += v.x * v.x + v.y * v.y + v.z * v.z + v.w * v.w;
    }
#pragma unroll
    for (int o = 16; o > 0; o >>= 1) s += __shfl_xor_sync(0xffffffffu, s, o);
    if (lane == 0) g_enorm[warp] = s;
}

// ---------------------------------------------------------------------------
// kernel: bf16 HMMA GEMM + approximate per-row argmin + candidate capture.
// CTA = 128 X-rows vs all 8192 codes. Warp w owns rows 16w..16w+15.
// A stored fragment-major in SMEM (built once, reused for all 64 n-tiles).
// B staged per 64-k chunk in SMEM (144B-padded rows, conflict-free b-frag LDS).
// ---------------------------------------------------------------------------
#define SM_AF 0
#define SM_BS 131072
#define SMEM_HMMA (131072 + 18432)

__device__ __forceinline__ void upd_cand(float s, int col, float& rm, int& cnt,
                                         int* cc, float* cf) {
    if (s <= rm + MARGIN) {
        if (cnt == CBUF) {
            float thr = rm + MARGIN;
            int wp = 0;
#pragma unroll
            for (int i = 0; i < CBUF; ++i)
                if (cf[i] <= thr) { cc[wp] = cc[i]; cf[wp] = cf[i]; ++wp; }
            cnt = wp;
            if (cnt == CBUF) {
                int mi = 0;
#pragma unroll
                for (int i = 1; i < CBUF; ++i)
                    if (cf[i] > cf[mi]) mi = i;
                cnt = CBUF - 1;
                cc[mi] = cc[cnt]; cf[mi] = cf[cnt];
            }
        }
        cc[cnt] = col; cf[cnt] = s; ++cnt;
        if (s < rm) rm = s;
    }
}

__global__ void __launch_bounds__(256, 1) k_hmma(const float* __restrict__ X) {
    extern __shared__ __align__(16) char smem[];
    const int tid = threadIdx.x;
    const int w   = tid >> 5;
    const int l   = tid & 31;
    const int m0  = blockIdx.x * 128;

    // ---- build A fragments (bf16) from fp32 X: entry e = (tile w', k16 s, lane)
    for (int e = tid; e < 8192; e += 256) {
        int tw = e >> 10, rem = e & 1023, s = rem >> 5, ll = rem & 31;
        int r = m0 + tw * 16 + (ll >> 2);
        int k = s * 16 + 2 * (ll & 3);
        const float* x0 = X + (size_t)r * DDIM + k;
        float2 v00 = *reinterpret_cast<const float2*>(x0);
        float2 v10 = *reinterpret_cast<const float2*>(x0 + 8 * DDIM);
        float2 v01 = *reinterpret_cast<const float2*>(x0 + 8);
        float2 v11 = *reinterpret_cast<const float2*>(x0 + 8 * DDIM + 8);
        uint4 u;
        u.x = packbf2(v00.x, v00.y);   // a0: (r,   k..k+1)
        u.y = packbf2(v10.x, v10.y);   // a1: (r+8, k..k+1)
        u.z = packbf2(v01.x, v01.y);   // a2: (r,   k+8..k+9)
        u.w = packbf2(v11.x, v11.y);   // a3: (r+8, k+8..k+9)
        *reinterpret_cast<uint4*>(smem + SM_AF + (size_t)e * 16) = u;
    }

    // ---- B prefetch (register double buffer, R5-validated pattern)
    uint4 pb[4];
    auto LDB = [&](int nt, int kc) {
#pragma unroll
        for (int i = 0; i < 4; ++i) {
            int f = tid + 256 * i;
            int row = f >> 3, q = f & 7;
            pb[i] = *reinterpret_cast<const uint4*>(
                reinterpret_cast<const char*>(g_ehi) +
                (size_t)(nt * 128 + row) * 1024 + kc * 128 + q * 16);
        }
    };
    LDB(0, 0);
    __syncthreads();   // A fragments visible

    // per-lane argmin state for rows r0 = m0+16w+(l>>2), r1 = r0+8
    float rm0 = __int_as_float(0x7f800000), rm1 = rm0;
    int   cnt0 = 0, cnt1 = 0;
    int   cc0[CBUF], cc1[CBUF];
    float cf0[CBUF], cf1[CBUF];

    for (int nt = 0; nt < KCODES / 128; ++nt) {
        float acc[16][4];
#pragma unroll
        for (int j = 0; j < 16; ++j)
#pragma unroll
            for (int q = 0; q < 4; ++q) acc[j][q] = 0.0f;

        for (int kc = 0; kc < 8; ++kc) {
            // store prefetched B chunk (row-major, 144B padded rows)
#pragma unroll
            for (int i = 0; i < 4; ++i) {
                int f = tid + 256 * i;
                int row = f >> 3, q = f & 7;
                *reinterpret_cast<uint4*>(smem + SM_BS + row * 144 + q * 16) = pb[i];
            }
            __syncthreads();
            {   // prefetch next chunk
                int nn = nt, nk = kc + 1;
                if (nk == 8) { nk = 0; ++nn; }
                if (nn < KCODES / 128) LDB(nn, nk);
            }
#pragma unroll
            for (int s = 0; s < 4; ++s) {
                uint4 af = *reinterpret_cast<const uint4*>(
                    smem + SM_AF + (size_t)(((w * 32) + (kc * 4 + s)) * 32 + l) * 16);
                const uint32_t* bw = reinterpret_cast<const uint32_t*>(smem + SM_BS);
                int wbase = s * 8 + (l & 3);
#pragma unroll
                for (int j = 0; j < 16; ++j) {
                    int col = j * 8 + (l >> 2);
                    uint32_t b0 = bw[col * 36 + wbase];
                    uint32_t b1 = bw[col * 36 + wbase + 4];
                    mma16816(acc[j][0], acc[j][1], acc[j][2], acc[j][3],
                             af.x, af.y, af.z, af.w, b0, b1);
                }
            }
            __syncthreads();   // all consumed before next store
        }

        // epilogue: scores s~ = en - 2*dot (xs cancels per-row); capture
#pragma unroll
        for (int j = 0; j < 16; ++j) {
            int col0 = nt * 128 + j * 8 + 2 * (l & 3);
            float2 en = __ldg(reinterpret_cast<const float2*>(g_enorm + col0));
            float s00 = fmaf(-2.0f, acc[j][0], en.x);
            float s01 = fmaf(-2.0f, acc[j][1], en.y);
            float s10 = fmaf(-2.0f, acc[j][2], en.x);
            float s11 = fmaf(-2.0f, acc[j][3], en.y);
            upd_cand(s00, col0,     rm0, cnt0, cc0, cf0);
            upd_cand(s01, col0 + 1, rm0, cnt0, cc0, cf0);
            upd_cand(s10, col0,     rm1, cnt1, cc1, cf1);
            upd_cand(s11, col0 + 1, rm1, cnt1, cc1, cf1);
        }
    }

    // global row-min across the 4 lanes sharing each row (lanes 4q..4q+3)
    float gm0 = rm0, gm1 = rm1;
    gm0 = fminf(gm0, __shfl_xor_sync(0xffffffffu, gm0, 1));
    gm0 = fminf(gm0, __shfl_xor_sync(0xffffffffu, gm0, 2));
    gm1 = fminf(gm1, __shfl_xor_sync(0xffffffffu, gm1, 1));
    gm1 = fminf(gm1, __shfl_xor_sync(0xffffffffu, gm1, 2));

    const int r0 = m0 + 16 * w + (l >> 2);
    const int r1 = r0 + 8;
    {
        float thr = gm0 + MARGIN;
        int kept = 0, tmp[CBUF];
        for (int i = 0; i < cnt0; ++i) if (cf0[i] <= thr) tmp[kept++] = cc0[i];
        if (kept) {
            int base = atomicAdd(&g_cnt[r0], kept);
            for (int i = 0; i < kept; ++i)
                if (base + i < 32) g_cand[(size_t)r0 * 32 + base + i] = tmp[i];
        }
    }
    {
        float thr = gm1 + MARGIN;
        int kept = 0, tmp[CBUF];
        for (int i = 0; i < cnt1; ++i) if (cf1[i] <= thr) tmp[kept++] = cc1[i];
        if (kept) {
            int base = atomicAdd(&g_cnt[r1], kept);
            for (int i = 0; i < kept; ++i)
                if (base + i < 32) g_cand[(size_t)r1 * 32 + base + i] = tmp[i];
        }
    }
}

// ---------------------------------------------------------------------------
// kernel: exact rescoring of candidates. Chain identical to the R5-validated
// epilogue: sequential-k single-accumulator fma, fl(fl(xs-2dot)+en), ties ->
// lowest index.
// ---------------------------------------------------------------------------
__global__ void __launch_bounds__(32) k_rescore(const float* __restrict__ X,
                                                const float* __restrict__ E) {
    __shared__ float sx[DDIM];
    const int row = blockIdx.x;
    const int t   = threadIdx.x;
    const float4* xr = reinterpret_cast<const float4*>(X + (size_t)row * DDIM);
#pragma unroll
    for (int r = 0; r < 4; ++r)
        reinterpret_cast<float4*>(sx)[t + 32 * r] = xr[t + 32 * r];
    __syncwarp();

    int cnt = g_cnt[row];
    if (cnt > 32) cnt = 32;
    float s  = __int_as_float(0x7f800000);
    int  col = 0x7fffffff;
    if (t < cnt) {
        col = g_cand[(size_t)row * 32 + t];
        const float* er = E + (size_t)col * DDIM;
        float acc = 0.0f;
#pragma unroll 8
        for (int k = 0; k < DDIM; ++k) acc = __fmaf_rn(sx[k], er[k], acc);
        s = __fadd_rn(__fadd_rn(g_xs[row], -2.0f * acc), g_enorm[col]);
    }
#pragma unroll
    for (int o = 16; o > 0; o >>= 1) {
        float vs = __shfl_down_sync(0xffffffffu, s, o);
        int   vc = __shfl_down_sync(0xffffffffu, col, o);
        if (vs < s || (vs == s && vc < col)) { s = vs; col = vc; }
    }
    if (t == 0) g_idx[row] = col;
}

// ---------------------------------------------------------------------------
// EMA update kernels (unchanged, validated in R5)
// ---------------------------------------------------------------------------
__global__ void k_init(const float* __restrict__ ew,
                       const float* __restrict__ ecs,
                       float* __restrict__ out) {
    size_t i = (size_t)blockIdx.x * blockDim.x + threadIdx.x;
    if (i < (size_t)KCODES * DDIM) out[OFF_W + i] = 0.99f * ew[i];
    if (i < (size_t)KCODES)        out[OFF_CS + i] = 0.99f * ecs[i];
}

__global__ void __launch_bounds__(128)
k_gather(const float* __restrict__ X, const float* __restrict__ E,
         float* __restrict__ out) {
    const int n   = blockIdx.x;
    const int t   = threadIdx.x;
    const int idx = g_idx[n];
    const float4 f = reinterpret_cast<const float4*>(X + (size_t)n * DDIM)[t];
    const float4 e = reinterpret_cast<const float4*>(E + (size_t)idx * DDIM)[t];
    float4 q;
    q.x = f.x + (e.x - f.x);
    q.y = f.y + (e.y - f.y);
    q.z = f.z + (e.z - f.z);
    q.w = f.w + (e.w - f.w);
    reinterpret_cast<float4*>(out + OFF_Q + (size_t)n * DDIM)[t] = q;
    float dx = f.x - q.x, dy = f.y - q.y, dz = f.z - q.z, dw = f.w - q.w;
    float local = dx * dx + dy * dy + dz * dz + dw * dw;

    const float om = (float)(1.0 - 0.99);
    float* wv = out + OFF_W + (size_t)idx * DDIM + (size_t)t * 4;
    atomicAdd(wv + 0, om * f.x);
    atomicAdd(wv + 1, om * f.y);
    atomicAdd(wv + 2, om * f.z);
    atomicAdd(wv + 3, om * f.w);

    __shared__ float red[128];
    red[t] = local;
    __syncthreads();
#pragma unroll
    for (int o = 64; o > 0; o >>= 1) {
        if (t < o) red[t] += red[t + o];
        __syncthreads();
    }
    if (t == 0) {
        atomicAdd(&g_sumsq, red[0]);
        out[OFF_T + n] = (float)idx;
        atomicAdd(out + OFF_CS + idx, om);
    }
}

__global__ void k_sumcs(const float* __restrict__ cs) {
    __shared__ float red[256];
    float s = 0.0f;
    for (int i = threadIdx.x; i < KCODES; i += 256) s += cs[i];
    red[threadIdx.x] = s;
    __syncthreads();
#pragma unroll
    for (int o = 128; o > 0; o >>= 1) {
        if (threadIdx.x < o) red[threadIdx.x] += red[threadIdx.x + o];
        __syncthreads();
    }
    if (threadIdx.x == 0) g_S = red[0];
}

__global__ void k_final(float* __restrict__ out) {
    size_t i = (size_t)blockIdx.x * blockDim.x + threadIdx.x;
    if (i == 0) out[OFF_L] = 0.25f * (g_sumsq / 8388608.0f);
    if (i >= (size_t)KCODES * DDIM) return;
    size_t k = i >> 9;
    float csn = (out[OFF_CS + k] + 1e-5f) / (g_S + (float)(8192 * 1e-5));
    out[OFF_E + i] = out[OFF_W + i] / csn;
}

// ---------------------------------------------------------------------------
extern "C" void kernel_launch(void* const* d_in, const int* in_sizes, int n_in,
                              void* d_out, int out_size) {
    const float* X   = (const float*)d_in[0];
    const float* E   = (const float*)d_in[1];
    const float* ecs = (const float*)d_in[2];
    const float* ew  = (const float*)d_in[3];
    float* out = (float*)d_out;

    cudaFuncSetAttribute(k_hmma, cudaFuncAttributeMaxDynamicSharedMemorySize,
                         SMEM_HMMA);

    k_splitE <<<(KCODES * DDIM + 255) / 256, 256>>>(E);
    k_xnorm  <<<N_ROWS * 8 / 256, 256>>>(X);
    k_enorm  <<<KCODES / 8, 256>>>(E);
    k_hmma   <<<N_ROWS / 128, 256, SMEM_HMMA>>>(X);
    k_rescore<<<N_ROWS, 32>>>(X, E);
    k_init   <<<(KCODES * DDIM + 255) / 256, 256>>>(ew, ecs, out);
    k_gather <<<N_ROWS, 128>>>(X, E, out);
    k_sumcs  <<<1, 256>>>(out + OFF_CS);
    k_final  <<<(KCODES * DDIM + 255) / 256, 256>>>(out);
}